// round 9
// baseline (speedup 1.0000x reference)
#include <cuda_runtime.h>
#include <cuda_bf16.h>
#include <math.h>
#include <stdint.h>
#include <string.h>

#define DIMC   384
#define HEADS  8
#define HD     48
#define NADLA  343
#define HWD    14
#define NTOK   2744
#define BATCH  8
#define MTOT   (BATCH*NTOK)
#define SCALE  0.14433756729740643f

__device__ float g_q   [(long long)MTOT*DIMC];
__device__ float g_kv  [(long long)MTOT*2*DIMC];
__device__ float g_adla[(long long)BATCH*NADLA*DIMC];
__device__ float g_pb  [(long long)HEADS*NADLA*NTOK];
__device__ float g_ab  [(long long)HEADS*NTOK*NADLA];
__device__ float g_adlav[(long long)BATCH*HEADS*NADLA*HD];
__device__ float g_attn[(long long)MTOT*DIMC];

static inline int cdiv(int a, int b) { return (a + b - 1) / b; }

__device__ __forceinline__ void fma2(float2& c, float2 a, float2 b)
{
    unsigned long long cc, aa, bb;
    memcpy(&cc, &c, 8); memcpy(&aa, &a, 8); memcpy(&bb, &b, 8);
    asm("fma.rn.f32x2 %0, %1, %2, %0;" : "+l"(cc) : "l"(aa), "l"(bb));
    memcpy(&c, &cc, 8);
}

// ---------------- dense NN sgemm (f32x2), tile 128x128x16, 8x8 thread tile,
// global->reg prefetch ----------------
#define BSROW 132
__global__ void __launch_bounds__(256)
sgemm_f2(const float* __restrict__ A, const float* __restrict__ B,
         float* __restrict__ C, const float* __restrict__ bias,
         int M, int N, int K)
{
    __shared__ float As[16][BSROW];   // As[k][m]
    __shared__ float Bs[16][BSROW];   // Bs[k][n]

    const int tid = threadIdx.x, tx = tid & 15, ty = tid >> 4;
    const int row0 = blockIdx.y * 128, col0 = blockIdx.x * 128;

    // staging maps
    const int ar = tid >> 1, akq = (tid & 1) * 8;   // A: row ar, k akq..akq+7
    const int bk = tid >> 4, bc = (tid & 15) * 8;   // B: k bk, col bc..bc+7

    float4 pa0, pa1, pb0, pb1;

    auto loadA = [&](int k0) {
        int gr = row0 + ar;
        if (gr < M) {
            const float* ap = A + (long long)gr * K + k0 + akq;
            pa0 = *(const float4*)(ap);
            pa1 = *(const float4*)(ap + 4);
        } else {
            pa0 = make_float4(0.f, 0.f, 0.f, 0.f);
            pa1 = pa0;
        }
    };
    auto loadB = [&](int k0) {
        const float* bp = B + (long long)(k0 + bk) * N + col0 + bc;
        pb0 = *(const float4*)(bp);
        pb1 = *(const float4*)(bp + 4);
    };
    auto storeStage = [&]() {
        As[akq + 0][ar] = pa0.x; As[akq + 1][ar] = pa0.y;
        As[akq + 2][ar] = pa0.z; As[akq + 3][ar] = pa0.w;
        As[akq + 4][ar] = pa1.x; As[akq + 5][ar] = pa1.y;
        As[akq + 6][ar] = pa1.z; As[akq + 7][ar] = pa1.w;
        *(float4*)&Bs[bk][bc] = pb0;
        *(float4*)&Bs[bk][bc + 4] = pb1;
    };

    float2 acc[4][8];
#pragma unroll
    for (int i = 0; i < 4; i++)
#pragma unroll
        for (int j = 0; j < 8; j++) acc[i][j] = make_float2(0.f, 0.f);

    loadA(0); loadB(0);
    storeStage();
    __syncthreads();

    for (int k0 = 16;; k0 += 16) {
        bool more = k0 < K;
        if (more) { loadA(k0); loadB(k0); }
#pragma unroll
        for (int kk = 0; kk < 16; kk++) {
            float4 a0 = *(const float4*)&As[kk][ty * 8];
            float4 a1 = *(const float4*)&As[kk][ty * 8 + 4];
            float4 b0 = *(const float4*)&Bs[kk][tx * 8];
            float4 b1 = *(const float4*)&Bs[kk][tx * 8 + 4];
            float2 ar2[4] = { make_float2(a0.x, a0.y), make_float2(a0.z, a0.w),
                              make_float2(a1.x, a1.y), make_float2(a1.z, a1.w) };
            float nb[8] = { b0.x, b0.y, b0.z, b0.w, b1.x, b1.y, b1.z, b1.w };
#pragma unroll
            for (int j = 0; j < 8; j++) {
                float2 bb = make_float2(nb[j], nb[j]);
#pragma unroll
                for (int i = 0; i < 4; i++) fma2(acc[i][j], ar2[i], bb);
            }
        }
        if (!more) break;
        __syncthreads();
        storeStage();
        __syncthreads();
    }

    float bx[8] = {0, 0, 0, 0, 0, 0, 0, 0};
    if (bias) {
#pragma unroll
        for (int j = 0; j < 8; j++) bx[j] = bias[col0 + tx * 8 + j];
    }
#pragma unroll
    for (int i = 0; i < 4; i++) {
        int gr0 = row0 + ty * 8 + 2 * i;
        long long base = (long long)gr0 * N + col0 + tx * 8;
        if (gr0 < M) {
            *(float4*)(C + base) =
                make_float4(acc[i][0].x + bx[0], acc[i][1].x + bx[1],
                            acc[i][2].x + bx[2], acc[i][3].x + bx[3]);
            *(float4*)(C + base + 4) =
                make_float4(acc[i][4].x + bx[4], acc[i][5].x + bx[5],
                            acc[i][6].x + bx[6], acc[i][7].x + bx[7]);
        }
        if (gr0 + 1 < M) {
            *(float4*)(C + base + N) =
                make_float4(acc[i][0].y + bx[0], acc[i][1].y + bx[1],
                            acc[i][2].y + bx[2], acc[i][3].y + bx[3]);
            *(float4*)(C + base + N + 4) =
                make_float4(acc[i][4].y + bx[4], acc[i][5].y + bx[5],
                            acc[i][6].y + bx[6], acc[i][7].y + bx[7]);
        }
    }
}

// ---------------- fused attention 1: 64 anchors/CTA, 128-token chunks ----------------
#define A1_ATH 0
#define A1_KST 3168            // [48][130]
#define A1_VS  9408            // [128][52]
#define A1_PS  16064           // [64][132]; reused as Osm [64][50]
#define A1_FAC 24512
#define A1_LNV 24576
#define A1_BYTES (24640*4)

__global__ void __launch_bounds__(256, 2) fused_att1(
    const float* __restrict__ adla, const float* __restrict__ kv,
    const float* __restrict__ pb, float* __restrict__ av)
{
    extern __shared__ float sm[];
    float* AthT = sm + A1_ATH;
    float* KsT  = sm + A1_KST;
    float* Vs   = sm + A1_VS;
    float* Ps   = sm + A1_PS;
    float* facs = sm + A1_FAC;
    float* lnv  = sm + A1_LNV;

    const int bh = blockIdx.y, b = bh >> 3, h = bh & 7;
    const int a0blk = blockIdx.x * 64;
    const int tid = threadIdx.x;
    // S mapping: thread = 4 anchors x 4 token-pairs (pairs strided 32)
    const int a4 = (tid >> 4) * 4, tg = tid & 15;
    const int tp = tg * 2;
    // O mapping
    const int d0 = (tid & 7) * 6, ts = (tid >> 3) & 3, a8 = (tid >> 5) * 8;
    // stage mapping
    const int srow = tid >> 1, scol = (tid & 1) * 24;

    for (int i = tid; i < 64 * 48; i += 256) {
        int a = i / 48, d = i - a * 48;
        int aG = a0blk + a;
        AthT[d * 66 + a] = (aG < NADLA)
            ? adla[((long long)(b * NADLA + aG)) * DIMC + h * HD + d] * SCALE : 0.f;
    }

    const float* pbr[4];
#pragma unroll
    for (int i = 0; i < 4; i++) {
        int aG = a0blk + a4 + i;
        pbr[i] = pb + ((long long)(h * NADLA + (aG < NADLA ? aG : NADLA - 1))) * NTOK;
    }

    float m[4], l[4];
#pragma unroll
    for (int i = 0; i < 4; i++) { m[i] = -INFINITY; l[i] = 0.f; }
    float2 O[8][3];
#pragma unroll
    for (int i = 0; i < 8; i++) O[i][0] = O[i][1] = O[i][2] = make_float2(0.f, 0.f);

    for (int c0 = 0; c0 < NTOK; c0 += 128) {
        {   // stage K^T and V
            int n = c0 + srow;
            bool ok = n < NTOK;
            const float* kb = kv + ((long long)(b * NTOK + (ok ? n : 0))) * 768 + h * HD + scol;
#pragma unroll
            for (int j = 0; j < 24; j += 4) {
                float4 kk = ok ? *(const float4*)(kb + j) : make_float4(0, 0, 0, 0);
                float4 vv = ok ? *(const float4*)(kb + 384 + j) : make_float4(0, 0, 0, 0);
                KsT[(scol + j + 0) * 130 + srow] = kk.x;
                KsT[(scol + j + 1) * 130 + srow] = kk.y;
                KsT[(scol + j + 2) * 130 + srow] = kk.z;
                KsT[(scol + j + 3) * 130 + srow] = kk.w;
                *(float4*)&Vs[srow * 52 + scol + j] = vv;
            }
        }
        __syncthreads();

        // S: 4 anchors x 4 token-pairs; acc[i][j] = (tok tp+32j, tok tp+1+32j)
        float2 acc[4][4];
#pragma unroll
        for (int i = 0; i < 4; i++)
#pragma unroll
            for (int j = 0; j < 4; j++) acc[i][j] = make_float2(0.f, 0.f);
#pragma unroll 4
        for (int d = 0; d < 48; d++) {
            float2 aL = *(const float2*)&AthT[d * 66 + a4];
            float2 aH = *(const float2*)&AthT[d * 66 + a4 + 2];
            const float* kr = &KsT[d * 130 + tp];
            float2 kp0 = *(const float2*)(kr);
            float2 kp1 = *(const float2*)(kr + 32);
            float2 kp2 = *(const float2*)(kr + 64);
            float2 kp3 = *(const float2*)(kr + 96);
            float2 A0 = make_float2(aL.x, aL.x), A1 = make_float2(aL.y, aL.y);
            float2 A2 = make_float2(aH.x, aH.x), A3 = make_float2(aH.y, aH.y);
            fma2(acc[0][0], A0, kp0); fma2(acc[0][1], A0, kp1);
            fma2(acc[0][2], A0, kp2); fma2(acc[0][3], A0, kp3);
            fma2(acc[1][0], A1, kp0); fma2(acc[1][1], A1, kp1);
            fma2(acc[1][2], A1, kp2); fma2(acc[1][3], A1, kp3);
            fma2(acc[2][0], A2, kp0); fma2(acc[2][1], A2, kp1);
            fma2(acc[2][2], A2, kp2); fma2(acc[2][3], A2, kp3);
            fma2(acc[3][0], A3, kp0); fma2(acc[3][1], A3, kp1);
            fma2(acc[3][2], A3, kp2); fma2(acc[3][3], A3, kp3);
        }
#pragma unroll
        for (int i = 0; i < 4; i++) {
            float2 s2[4];
            float mx = -INFINITY;
#pragma unroll
            for (int j = 0; j < 4; j++) {
                int n = c0 + tp + 32 * j;
                float2 sv = acc[i][j];
                if (n + 1 < NTOK) {
                    float2 pbv = *(const float2*)(pbr[i] + n);
                    sv.x += pbv.x; sv.y += pbv.y;
                } else {
                    sv.x = (n < NTOK) ? sv.x + pbr[i][n] : -INFINITY;
                    sv.y = -INFINITY;
                }
                s2[j] = sv;
                mx = fmaxf(mx, fmaxf(sv.x, sv.y));
            }
#pragma unroll
            for (int o = 1; o < 16; o <<= 1)
                mx = fmaxf(mx, __shfl_xor_sync(0xffffffffu, mx, o));
            float mn = fmaxf(m[i], mx);
            float sum = 0.f;
#pragma unroll
            for (int j = 0; j < 4; j++) {
                float px = __expf(s2[j].x - mn);
                float py = __expf(s2[j].y - mn);
                *(float2*)&Ps[(a4 + i) * 132 + tp + 32 * j] = make_float2(px, py);
                sum += px + py;
            }
#pragma unroll
            for (int o = 1; o < 16; o <<= 1)
                sum += __shfl_xor_sync(0xffffffffu, sum, o);
            float fac = __expf(m[i] - mn);
            l[i] = l[i] * fac + sum;
            m[i] = mn;
            if (tg == 0) facs[a4 + i] = fac;
        }
        __syncthreads();

        // O: thread = 8 anchors x 6 dims, token-quarter ts
        {
#pragma unroll
            for (int i = 0; i < 8; i++) {
                float f = facs[a8 + i];
                O[i][0].x *= f; O[i][0].y *= f;
                O[i][1].x *= f; O[i][1].y *= f;
                O[i][2].x *= f; O[i][2].y *= f;
            }
#pragma unroll 2
            for (int jj = 0; jj < 32; jj++) {
                int j = 4 * jj + ts;
                const float* vr = &Vs[j * 52 + d0];
                float2 v0 = *(const float2*)(vr);
                float2 v1 = *(const float2*)(vr + 2);
                float2 v2 = *(const float2*)(vr + 4);
#pragma unroll
                for (int i = 0; i < 8; i++) {
                    float p = Ps[(a8 + i) * 132 + j];
                    float2 pp = make_float2(p, p);
                    fma2(O[i][0], pp, v0);
                    fma2(O[i][1], pp, v1);
                    fma2(O[i][2], pp, v2);
                }
            }
        }
        __syncthreads();
    }

    if (tg == 0) {
#pragma unroll
        for (int i = 0; i < 4; i++) lnv[a4 + i] = 1.f / l[i];
    }
    float* Osm = Ps;  // [64][50]
    if (ts == 0) {
#pragma unroll
        for (int i = 0; i < 8; i++) {
            float* dst = &Osm[(a8 + i) * 50 + d0];
            *(float2*)(dst) = O[i][0]; *(float2*)(dst + 2) = O[i][1]; *(float2*)(dst + 4) = O[i][2];
        }
    }
    __syncthreads();
#pragma unroll
    for (int k = 1; k < 4; k++) {
        if (ts == k) {
#pragma unroll
            for (int i = 0; i < 8; i++) {
                float* dst = &Osm[(a8 + i) * 50 + d0];
                float2 t0 = *(float2*)(dst), t1 = *(float2*)(dst + 2), t2 = *(float2*)(dst + 4);
                t0.x += O[i][0].x; t0.y += O[i][0].y;
                t1.x += O[i][1].x; t1.y += O[i][1].y;
                t2.x += O[i][2].x; t2.y += O[i][2].y;
                *(float2*)(dst) = t0; *(float2*)(dst + 2) = t1; *(float2*)(dst + 4) = t2;
            }
        }
        __syncthreads();
    }
    for (int i = tid; i < 64 * 48; i += 256) {
        int a = i / 48, d = i - a * 48;
        int aG = a0blk + a;
        if (aG < NADLA)
            av[((long long)bh * NADLA + aG) * HD + d] = Osm[a * 50 + d] * lnv[a];
    }
}

// ---------------- fused attention 2: 64 rows/CTA, anchors resident ----------------
#define A2_U   0               // AthT[48][352] then V[343][52]
#define A2_LS  17900           // Ls[64][360]
#define A2_QS  40940           // qT[48][66] then Osm[64][50]
#define A2_LNV 44140
#define A2_BYTES (44204*4)

__global__ void __launch_bounds__(512, 1) fused_att2(
    const float* __restrict__ q, const float* __restrict__ adla,
    const float* __restrict__ av, const float* __restrict__ ab,
    float* __restrict__ attn)
{
    extern __shared__ float sm[];
    float* U   = sm + A2_U;
    float* Ls  = sm + A2_LS;
    float* QS  = sm + A2_QS;
    float* lnv = sm + A2_LNV;

    const int bh = blockIdx.y, b = bh >> 3, h = bh & 7;
    const int n0 = blockIdx.x * 64;
    const int tid = threadIdx.x;

    for (int i = tid; i < 48 * 352; i += 512) {
        int d = i / 352, a = i - d * 352;
        U[i] = (a < NADLA) ? adla[((long long)(b * NADLA + a)) * DIMC + h * HD + d] : 0.f;
    }
    for (int i = tid; i < 64 * 48; i += 512) {
        int r = i / 48, d = i - r * 48;
        int n = n0 + r; int nC = n < NTOK ? n : NTOK - 1;
        QS[d * 66 + r] = q[((long long)(b * NTOK + nC)) * DIMC + h * HD + d] * SCALE;
    }
    __syncthreads();

    // phase A: thread = 4 rows x 22 anchors, 2-way d-split
    {
        const int dsel = tid >> 8, rem = tid & 255;
        const int r0 = (rem >> 4) * 4, a0 = (rem & 15) * 22;
        float2 acc[4][11];
#pragma unroll
        for (int i = 0; i < 4; i++)
#pragma unroll
            for (int j = 0; j < 11; j++) acc[i][j] = make_float2(0.f, 0.f);
        const int dbase = dsel * 24;
#pragma unroll 2
        for (int dd = 0; dd < 24; dd++) {
            int d = dbase + dd;
            float2 q01 = *(const float2*)&QS[d * 66 + r0];
            float2 q23 = *(const float2*)&QS[d * 66 + r0 + 2];
            float2 Q0 = make_float2(q01.x, q01.x), Q1 = make_float2(q01.y, q01.y);
            float2 Q2 = make_float2(q23.x, q23.x), Q3 = make_float2(q23.y, q23.y);
            const float* ar = &U[d * 352 + a0];
#pragma unroll
            for (int j = 0; j < 11; j++) {
                float2 Ar = *(const float2*)(ar + 2 * j);
                fma2(acc[0][j], Q0, Ar); fma2(acc[1][j], Q1, Ar);
                fma2(acc[2][j], Q2, Ar); fma2(acc[3][j], Q3, Ar);
            }
        }
        if (dsel == 0) {
#pragma unroll
            for (int i = 0; i < 4; i++) {
                int n = n0 + r0 + i; int nC = n < NTOK ? n : NTOK - 1;
                const float* abr = ab + ((long long)(h * NTOK + nC)) * NADLA;
#pragma unroll
                for (int j = 0; j < 11; j++) {
                    int a = a0 + 2 * j;
                    if (a < NADLA)     Ls[(r0 + i) * 360 + a]     = acc[i][j].x + abr[a];
                    if (a + 1 < NADLA) Ls[(r0 + i) * 360 + a + 1] = acc[i][j].y + abr[a + 1];
                }
            }
        }
        __syncthreads();
        if (dsel == 1) {
#pragma unroll
            for (int i = 0; i < 4; i++)
#pragma unroll
                for (int j = 0; j < 11; j++) {
                    int a = a0 + 2 * j;
                    if (a < NADLA)     Ls[(r0 + i) * 360 + a]     += acc[i][j].x;
                    if (a + 1 < NADLA) Ls[(r0 + i) * 360 + a + 1] += acc[i][j].y;
                }
        }
        __syncthreads();
    }

    // stage V into U (AthT dead) + phase B softmax
    for (int i = tid; i < NADLA * 48; i += 512) {
        int a = i / 48, c = i - a * 48;
        U[a * 52 + c] = av[((long long)bh * NADLA + a) * HD + c];
    }
    {
        const int r = tid >> 3, t8 = tid & 7;
        float mx = -INFINITY;
        for (int a = t8; a < NADLA; a += 8) mx = fmaxf(mx, Ls[r * 360 + a]);
#pragma unroll
        for (int o = 1; o < 8; o <<= 1)
            mx = fmaxf(mx, __shfl_xor_sync(0xffffffffu, mx, o));
        float sum = 0.f;
        for (int a = t8; a < NADLA; a += 8) {
            float pv = __expf(Ls[r * 360 + a] - mx);
            Ls[r * 360 + a] = pv;
            sum += pv;
        }
#pragma unroll
        for (int o = 1; o < 8; o <<= 1)
            sum += __shfl_xor_sync(0xffffffffu, sum, o);
        if (t8 == 0) lnv[r] = 1.f / sum;
    }
    __syncthreads();

    // phase C: thread = 8 rows x 6 dims, anchor-eighth
    {
        const int d0 = (tid & 7) * 6;
        const int as = (tid >> 3) & 7;
        const int r0 = (tid >> 6) * 8;
        float2 acc[8][3];
#pragma unroll
        for (int i = 0; i < 8; i++) acc[i][0] = acc[i][1] = acc[i][2] = make_float2(0.f, 0.f);
        for (int a = as; a < NADLA; a += 8) {
            const float* vr = &U[a * 52 + d0];
            float2 v0 = *(const float2*)(vr);
            float2 v1 = *(const float2*)(vr + 2);
            float2 v2 = *(const float2*)(vr + 4);
#pragma unroll
            for (int i = 0; i < 8; i++) {
                float pv = Ls[(r0 + i) * 360 + a];
                float2 pp = make_float2(pv, pv);
                fma2(acc[i][0], pp, v0); fma2(acc[i][1], pp, v1); fma2(acc[i][2], pp, v2);
            }
        }
        __syncthreads();
        float* Osm = QS;  // [64][50]
        if (as == 0) {
#pragma unroll
            for (int i = 0; i < 8; i++) {
                float* dst = &Osm[(r0 + i) * 50 + d0];
                *(float2*)(dst) = acc[i][0]; *(float2*)(dst + 2) = acc[i][1]; *(float2*)(dst + 4) = acc[i][2];
            }
        }
        __syncthreads();
#pragma unroll
        for (int k = 1; k < 8; k++) {
            if (as == k) {
#pragma unroll
                for (int i = 0; i < 8; i++) {
                    float* dst = &Osm[(r0 + i) * 50 + d0];
                    float2 t0 = *(float2*)(dst), t1 = *(float2*)(dst + 2), t2 = *(float2*)(dst + 4);
                    t0.x += acc[i][0].x; t0.y += acc[i][0].y;
                    t1.x += acc[i][1].x; t1.y += acc[i][1].y;
                    t2.x += acc[i][2].x; t2.y += acc[i][2].y;
                    *(float2*)(dst) = t0; *(float2*)(dst + 2) = t1; *(float2*)(dst + 4) = t2;
                }
            }
            __syncthreads();
        }
    }
    for (int i = tid; i < 64 * 48; i += 512) {
        int r = i / 48, d = i - r * 48;
        int n = n0 + r;
        if (n < NTOK)
            attn[((long long)(b * NTOK + n)) * DIMC + h * HD + d] = QS[r * 50 + d] * lnv[r];
    }
}

// ---------------- pooling ----------------
__global__ void pool_adla(const float* __restrict__ q, float* __restrict__ adla)
{
    int idx = blockIdx.x * 256 + threadIdx.x;
    if (idx >= BATCH * NADLA * DIMC) return;
    int c = idx % DIMC;
    int a = (idx / DIMC) % NADLA;
    int b = idx / (DIMC * NADLA);
    int a1 = a / 49, a2 = (a / 7) % 7, a3 = a % 7;
    float s = 0.f;
#pragma unroll
    for (int i = 0; i < 2; i++)
#pragma unroll
        for (int j = 0; j < 2; j++)
#pragma unroll
            for (int k = 0; k < 2; k++) {
                int n = ((2 * a1 + i) * HWD + (2 * a2 + j)) * HWD + (2 * a3 + k);
                s += q[((long long)(b * NTOK + n)) * DIMC + c];
            }
    adla[idx] = s * 0.125f;
}

// ---------------- bias tables ----------------
__device__ __forceinline__ void lin_w(int o, int& i0, int& i1, float& w)
{
    float x = 0.5f * o - 0.25f;
    x = fminf(fmaxf(x, 0.f), 6.f);
    i0 = (int)floorf(x);
    i1 = min(i0 + 1, 6);
    w = x - (float)i0;
}

__device__ __forceinline__ float interp3(const float* base, int x, int y, int z)
{
    int x0, x1, y0, y1, z0, z1;
    float wx, wy, wz;
    lin_w(x, x0, x1, wx); lin_w(y, y0, y1, wy); lin_w(z, z0, z1, wz);
    float c000 = base[x0 * 49 + y0 * 7 + z0], c001 = base[x0 * 49 + y0 * 7 + z1];
    float c010 = base[x0 * 49 + y1 * 7 + z0], c011 = base[x0 * 49 + y1 * 7 + z1];
    float c100 = base[x1 * 49 + y0 * 7 + z0], c101 = base[x1 * 49 + y0 * 7 + z1];
    float c110 = base[x1 * 49 + y1 * 7 + z0], c111 = base[x1 * 49 + y1 * 7 + z1];
    float v0 = (1.f - wy) * ((1.f - wz) * c000 + wz * c001) + wy * ((1.f - wz) * c010 + wz * c011);
    float v1 = (1.f - wy) * ((1.f - wz) * c100 + wz * c101) + wy * ((1.f - wz) * c110 + wz * c111);
    return (1.f - wx) * v0 + wx * v1;
}

__global__ void pb_kernel(const float* __restrict__ an, const float* __restrict__ ah,
                          const float* __restrict__ aw, const float* __restrict__ ad,
                          float* __restrict__ pb)
{
    int idx = blockIdx.x * 256 + threadIdx.x;
    if (idx >= HEADS * NADLA * NTOK) return;
    int n = idx % NTOK;
    int a = (idx / NTOK) % NADLA;
    int h = idx / (NTOK * NADLA);
    int x = n / 196, y = (n / 14) % 14, z = n % 14;
    const float* base = an + ((long long)(h * NADLA + a)) * NADLA;
    float v = interp3(base, x, y, z);
    v += ah[(h * NADLA + a) * HWD + x];
    v += aw[(h * NADLA + a) * HWD + y];
    v += ad[(h * NADLA + a) * HWD + z];
    pb[idx] = v;
}

__global__ void ab_kernel(const float* __restrict__ na, const float* __restrict__ ha,
                          const float* __restrict__ wa, const float* __restrict__ da,
                          float* __restrict__ ab)
{
    int idx = blockIdx.x * 256 + threadIdx.x;
    if (idx >= HEADS * NTOK * NADLA) return;
    int a = idx % NADLA;
    int n = (idx / NADLA) % NTOK;
    int h = idx / (NADLA * NTOK);
    int x = n / 196, y = (n / 14) % 14, z = n % 14;
    const float* base = na + ((long long)(h * NADLA + a)) * NADLA;
    float v = interp3(base, x, y, z);
    v += ha[(h * HWD + x) * NADLA + a];
    v += wa[(h * HWD + y) * NADLA + a];
    v += da[(h * HWD + z) * NADLA + a];
    ab[idx] = v;
}

// ---------------- depthwise 3x3x3 conv, += into attn ----------------
__global__ void dwc_add(const float* __restrict__ kv, const float* __restrict__ w,
                        const float* __restrict__ bias, float* __restrict__ attn)
{
    int blk = blockIdx.x;
    int c = threadIdx.x;
    int b = blk / NTOK, n = blk % NTOK;
    int x = n / 196, y = (n / 14) % 14, z = n % 14;
    float acc = bias[c];
    const float* wc = w + c * 27;
#pragma unroll
    for (int i = -1; i <= 1; i++) {
        int xx = x + i;
        if ((unsigned)xx >= (unsigned)HWD) continue;
#pragma unroll
        for (int j = -1; j <= 1; j++) {
            int yy = y + j;
            if ((unsigned)yy >= (unsigned)HWD) continue;
#pragma unroll
            for (int k = -1; k <= 1; k++) {
                int zz = z + k;
                if ((unsigned)zz >= (unsigned)HWD) continue;
                int nn = (xx * HWD + yy) * HWD + zz;
                acc = fmaf(kv[((long long)(b * NTOK + nn)) * 768 + DIMC + c],
                           wc[(i + 1) * 9 + (j + 1) * 3 + (k + 1)], acc);
            }
        }
    }
    attn[(long long)blk * DIMC + c] += acc;
}

// ---------------- launcher ----------------
extern "C" void kernel_launch(void* const* d_in, const int* in_sizes, int n_in,
                              void* d_out, int out_size)
{
    const float* x     = (const float*)d_in[0];
    const float* Wq    = (const float*)d_in[1];
    const float* Wkv   = (const float*)d_in[2];
    const float* Wproj = (const float*)d_in[3];
    const float* bproj = (const float*)d_in[4];
    const float* dwcw  = (const float*)d_in[5];
    const float* dwcb  = (const float*)d_in[6];
    const float* an    = (const float*)d_in[7];
    const float* na    = (const float*)d_in[8];
    const float* ah    = (const float*)d_in[9];
    const float* aw    = (const float*)d_in[10];
    const float* ad    = (const float*)d_in[11];
    const float* ha    = (const float*)d_in[12];
    const float* wa    = (const float*)d_in[13];
    const float* da    = (const float*)d_in[14];
    float* out = (float*)d_out;

    void* p;
    cudaGetSymbolAddress(&p, g_q);     float* q    = (float*)p;
    cudaGetSymbolAddress(&p, g_kv);    float* kv   = (float*)p;
    cudaGetSymbolAddress(&p, g_adla);  float* adla = (float*)p;
    cudaGetSymbolAddress(&p, g_pb);    float* pb   = (float*)p;
    cudaGetSymbolAddress(&p, g_ab);    float* ab   = (float*)p;
    cudaGetSymbolAddress(&p, g_adlav); float* av   = (float*)p;
    cudaGetSymbolAddress(&p, g_attn);  float* at   = (float*)p;

    cudaFuncSetAttribute(fused_att1, cudaFuncAttributeMaxDynamicSharedMemorySize, A1_BYTES);
    cudaFuncSetAttribute(fused_att2, cudaFuncAttributeMaxDynamicSharedMemorySize, A2_BYTES);

    sgemm_f2<<<dim3(DIMC / 128, cdiv(MTOT, 128)), 256>>>(x, Wq, q, nullptr, MTOT, DIMC, DIMC);
    sgemm_f2<<<dim3(768 / 128, cdiv(MTOT, 128)), 256>>>(x, Wkv, kv, nullptr, MTOT, 768, DIMC);
    pool_adla<<<cdiv(BATCH * NADLA * DIMC, 256), 256>>>(q, adla);
    pb_kernel<<<cdiv(HEADS * NADLA * NTOK, 256), 256>>>(an, ah, aw, ad, pb);
    ab_kernel<<<cdiv(HEADS * NTOK * NADLA, 256), 256>>>(na, ha, wa, da, ab);
    fused_att1<<<dim3(cdiv(NADLA, 64), BATCH * HEADS), 256, A1_BYTES>>>(adla, kv, pb, av);
    fused_att2<<<dim3(cdiv(NTOK, 64), BATCH * HEADS), 512, A2_BYTES>>>(q, adla, av, ab, at);
    dwc_add<<<BATCH * NTOK, DIMC>>>(kv, dwcw, dwcb, at);
    sgemm_f2<<<dim3(DIMC / 128, cdiv(MTOT, 128)), 256>>>(at, Wproj, out, bproj, MTOT, DIMC, DIMC);
}

// round 10
// speedup vs baseline: 1.0361x; 1.0361x over previous
#include <cuda_runtime.h>
#include <cuda_bf16.h>
#include <math.h>
#include <stdint.h>
#include <string.h>

#define DIMC   384
#define HEADS  8
#define HD     48
#define NADLA  343
#define HWD    14
#define NTOK   2744
#define BATCH  8
#define MTOT   (BATCH*NTOK)
#define SCALE  0.14433756729740643f

__device__ float g_q   [(long long)MTOT*DIMC];
__device__ float g_kv  [(long long)MTOT*2*DIMC];
__device__ float g_adla[(long long)BATCH*NADLA*DIMC];
__device__ float g_pb  [(long long)HEADS*NADLA*NTOK];
__device__ float g_ab  [(long long)HEADS*NTOK*NADLA];
__device__ float g_adlav[(long long)BATCH*HEADS*NADLA*HD];
__device__ float g_attn[(long long)MTOT*DIMC];

static inline int cdiv(int a, int b) { return (a + b - 1) / b; }

__device__ __forceinline__ void fma2(float2& c, float2 a, float2 b)
{
    unsigned long long cc, aa, bb;
    memcpy(&cc, &c, 8); memcpy(&aa, &a, 8); memcpy(&bb, &b, 8);
    asm("fma.rn.f32x2 %0, %1, %2, %0;" : "+l"(cc) : "l"(aa), "l"(bb));
    memcpy(&c, &cc, 8);
}

// ---------------- dense NN sgemm (f32x2), tile 128x128x16, 8x8 thread tile,
// single-buffered smem (no register prefetch -> no spill) ----------------
__global__ void __launch_bounds__(256)
sgemm_f2(const float* __restrict__ A, const float* __restrict__ B,
         float* __restrict__ C, const float* __restrict__ bias,
         int M, int N, int K)
{
    __shared__ float As[16][132];   // As[k][m]
    __shared__ float Bs[16][132];   // Bs[k][n]

    const int tid = threadIdx.x, tx = tid & 15, ty = tid >> 4;
    const int row0 = blockIdx.y * 128, col0 = blockIdx.x * 128;

    const int ar = tid >> 1, akq = (tid & 1) * 8;   // A staging
    const int bk = tid >> 4, bc = (tid & 15) * 8;   // B staging

    float2 acc[4][8];
#pragma unroll
    for (int i = 0; i < 4; i++)
#pragma unroll
        for (int j = 0; j < 8; j++) acc[i][j] = make_float2(0.f, 0.f);

    for (int k0 = 0; k0 < K; k0 += 16) {
        {
            int gr = row0 + ar;
            float4 v0 = make_float4(0.f, 0.f, 0.f, 0.f), v1 = v0;
            if (gr < M) {
                const float* ap = A + (long long)gr * K + k0 + akq;
                v0 = *(const float4*)(ap);
                v1 = *(const float4*)(ap + 4);
            }
            As[akq + 0][ar] = v0.x; As[akq + 1][ar] = v0.y;
            As[akq + 2][ar] = v0.z; As[akq + 3][ar] = v0.w;
            As[akq + 4][ar] = v1.x; As[akq + 5][ar] = v1.y;
            As[akq + 6][ar] = v1.z; As[akq + 7][ar] = v1.w;
            const float* bp = B + (long long)(k0 + bk) * N + col0 + bc;
            *(float4*)&Bs[bk][bc]     = *(const float4*)(bp);
            *(float4*)&Bs[bk][bc + 4] = *(const float4*)(bp + 4);
        }
        __syncthreads();
#pragma unroll
        for (int kk = 0; kk < 16; kk++) {
            float4 a0 = *(const float4*)&As[kk][ty * 8];
            float4 a1 = *(const float4*)&As[kk][ty * 8 + 4];
            float4 b0 = *(const float4*)&Bs[kk][tx * 8];
            float4 b1 = *(const float4*)&Bs[kk][tx * 8 + 4];
            float2 ar2[4] = { make_float2(a0.x, a0.y), make_float2(a0.z, a0.w),
                              make_float2(a1.x, a1.y), make_float2(a1.z, a1.w) };
            float nb[8] = { b0.x, b0.y, b0.z, b0.w, b1.x, b1.y, b1.z, b1.w };
#pragma unroll
            for (int j = 0; j < 8; j++) {
                float2 bb = make_float2(nb[j], nb[j]);
#pragma unroll
                for (int i = 0; i < 4; i++) fma2(acc[i][j], ar2[i], bb);
            }
        }
        __syncthreads();
    }

    float bx[8] = {0, 0, 0, 0, 0, 0, 0, 0};
    if (bias) {
#pragma unroll
        for (int j = 0; j < 8; j++) bx[j] = bias[col0 + tx * 8 + j];
    }
#pragma unroll
    for (int i = 0; i < 4; i++) {
        int gr0 = row0 + ty * 8 + 2 * i;
        long long base = (long long)gr0 * N + col0 + tx * 8;
        if (gr0 < M) {
            *(float4*)(C + base) =
                make_float4(acc[i][0].x + bx[0], acc[i][1].x + bx[1],
                            acc[i][2].x + bx[2], acc[i][3].x + bx[3]);
            *(float4*)(C + base + 4) =
                make_float4(acc[i][4].x + bx[4], acc[i][5].x + bx[5],
                            acc[i][6].x + bx[6], acc[i][7].x + bx[7]);
        }
        if (gr0 + 1 < M) {
            *(float4*)(C + base + N) =
                make_float4(acc[i][0].y + bx[0], acc[i][1].y + bx[1],
                            acc[i][2].y + bx[2], acc[i][3].y + bx[3]);
            *(float4*)(C + base + N + 4) =
                make_float4(acc[i][4].y + bx[4], acc[i][5].y + bx[5],
                            acc[i][6].y + bx[6], acc[i][7].y + bx[7]);
        }
    }
}

// ---------------- fused attention 1: 64 anchors/CTA, 128-token chunks ----------------
#define A1_ATH 0
#define A1_KST 3168            // [48][130]
#define A1_VS  9408            // [128][52]
#define A1_PS  16064           // [64][132]; reused as Osm [64][50]
#define A1_FAC 24512
#define A1_LNV 24576
#define A1_BYTES (24640*4)

__global__ void __launch_bounds__(256, 2) fused_att1(
    const float* __restrict__ adla, const float* __restrict__ kv,
    const float* __restrict__ pb, float* __restrict__ av)
{
    extern __shared__ float sm[];
    float* AthT = sm + A1_ATH;
    float* KsT  = sm + A1_KST;
    float* Vs   = sm + A1_VS;
    float* Ps   = sm + A1_PS;
    float* facs = sm + A1_FAC;
    float* lnv  = sm + A1_LNV;

    const int bh = blockIdx.y, b = bh >> 3, h = bh & 7;
    const int a0blk = blockIdx.x * 64;
    const int tid = threadIdx.x;
    const int a4 = (tid >> 4) * 4, tg = tid & 15;
    const int d0 = (tid & 7) * 6, ts = (tid >> 3) & 3, a8 = (tid >> 5) * 8;
    const int srow = tid >> 1, scol = (tid & 1) * 24;

    for (int i = tid; i < 64 * 48; i += 256) {
        int a = i / 48, d = i - a * 48;
        int aG = a0blk + a;
        AthT[d * 66 + a] = (aG < NADLA)
            ? adla[((long long)(b * NADLA + aG)) * DIMC + h * HD + d] * SCALE : 0.f;
    }

    const float* pbr[4];
#pragma unroll
    for (int i = 0; i < 4; i++) {
        int aG = a0blk + a4 + i;
        pbr[i] = pb + ((long long)(h * NADLA + (aG < NADLA ? aG : NADLA - 1))) * NTOK;
    }

    float m[4], l[4];
#pragma unroll
    for (int i = 0; i < 4; i++) { m[i] = -INFINITY; l[i] = 0.f; }
    float2 O[8][3];
#pragma unroll
    for (int i = 0; i < 8; i++) O[i][0] = O[i][1] = O[i][2] = make_float2(0.f, 0.f);

    for (int c0 = 0; c0 < NTOK; c0 += 128) {
        {   // stage K^T and V
            int n = c0 + srow;
            bool ok = n < NTOK;
            const float* kb = kv + ((long long)(b * NTOK + (ok ? n : 0))) * 768 + h * HD + scol;
#pragma unroll
            for (int j = 0; j < 24; j += 4) {
                float4 kk = ok ? *(const float4*)(kb + j) : make_float4(0, 0, 0, 0);
                float4 vv = ok ? *(const float4*)(kb + 384 + j) : make_float4(0, 0, 0, 0);
                KsT[(scol + j + 0) * 130 + srow] = kk.x;
                KsT[(scol + j + 1) * 130 + srow] = kk.y;
                KsT[(scol + j + 2) * 130 + srow] = kk.z;
                KsT[(scol + j + 3) * 130 + srow] = kk.w;
                *(float4*)&Vs[srow * 52 + scol + j] = vv;
            }
        }
        __syncthreads();

        // S: thread = 4 anchors x 8 tokens (strided by 16)
        float2 acc[8][2];
#pragma unroll
        for (int j = 0; j < 8; j++) acc[j][0] = acc[j][1] = make_float2(0.f, 0.f);
#pragma unroll 4
        for (int d = 0; d < 48; d++) {
            float2 aL = *(const float2*)&AthT[d * 66 + a4];
            float2 aH = *(const float2*)&AthT[d * 66 + a4 + 2];
            const float* kr = &KsT[d * 130 + tg];
#pragma unroll
            for (int j = 0; j < 8; j++) {
                float kx = kr[16 * j];
                float2 kk = make_float2(kx, kx);
                fma2(acc[j][0], aL, kk);
                fma2(acc[j][1], aH, kk);
            }
        }
#pragma unroll
        for (int i = 0; i < 4; i++) {
            float s[8];
            float mx = -INFINITY;
#pragma unroll
            for (int j = 0; j < 8; j++) {
                int n = c0 + tg + 16 * j;
                float sv = (i & 1) ? acc[j][i >> 1].y : acc[j][i >> 1].x;
                s[j] = (n < NTOK) ? sv + pbr[i][n] : -INFINITY;
                mx = fmaxf(mx, s[j]);
            }
#pragma unroll
            for (int o = 1; o < 16; o <<= 1)
                mx = fmaxf(mx, __shfl_xor_sync(0xffffffffu, mx, o));
            float mn = fmaxf(m[i], mx);
            float sum = 0.f;
#pragma unroll
            for (int j = 0; j < 8; j++) {
                float pv = __expf(s[j] - mn);
                Ps[(a4 + i) * 132 + tg + 16 * j] = pv;
                sum += pv;
            }
#pragma unroll
            for (int o = 1; o < 16; o <<= 1)
                sum += __shfl_xor_sync(0xffffffffu, sum, o);
            float fac = __expf(m[i] - mn);
            l[i] = l[i] * fac + sum;
            m[i] = mn;
            if (tg == 0) facs[a4 + i] = fac;
        }
        __syncthreads();

        // O: thread = 8 anchors x 6 dims, token-quarter ts
        {
#pragma unroll
            for (int i = 0; i < 8; i++) {
                float f = facs[a8 + i];
                O[i][0].x *= f; O[i][0].y *= f;
                O[i][1].x *= f; O[i][1].y *= f;
                O[i][2].x *= f; O[i][2].y *= f;
            }
#pragma unroll 2
            for (int jj = 0; jj < 32; jj++) {
                int j = 4 * jj + ts;
                const float* vr = &Vs[j * 52 + d0];
                float2 v0 = *(const float2*)(vr);
                float2 v1 = *(const float2*)(vr + 2);
                float2 v2 = *(const float2*)(vr + 4);
#pragma unroll
                for (int i = 0; i < 8; i++) {
                    float p = Ps[(a8 + i) * 132 + j];
                    float2 pp = make_float2(p, p);
                    fma2(O[i][0], pp, v0);
                    fma2(O[i][1], pp, v1);
                    fma2(O[i][2], pp, v2);
                }
            }
        }
        __syncthreads();
    }

    if (tg == 0) {
#pragma unroll
        for (int i = 0; i < 4; i++) lnv[a4 + i] = 1.f / l[i];
    }
    float* Osm = Ps;  // [64][50]
    if (ts == 0) {
#pragma unroll
        for (int i = 0; i < 8; i++) {
            float* dst = &Osm[(a8 + i) * 50 + d0];
            *(float2*)(dst) = O[i][0]; *(float2*)(dst + 2) = O[i][1]; *(float2*)(dst + 4) = O[i][2];
        }
    }
    __syncthreads();
#pragma unroll
    for (int k = 1; k < 4; k++) {
        if (ts == k) {
#pragma unroll
            for (int i = 0; i < 8; i++) {
                float* dst = &Osm[(a8 + i) * 50 + d0];
                float2 t0 = *(float2*)(dst), t1 = *(float2*)(dst + 2), t2 = *(float2*)(dst + 4);
                t0.x += O[i][0].x; t0.y += O[i][0].y;
                t1.x += O[i][1].x; t1.y += O[i][1].y;
                t2.x += O[i][2].x; t2.y += O[i][2].y;
                *(float2*)(dst) = t0; *(float2*)(dst + 2) = t1; *(float2*)(dst + 4) = t2;
            }
        }
        __syncthreads();
    }
    for (int i = tid; i < 64 * 48; i += 256) {
        int a = i / 48, d = i - a * 48;
        int aG = a0blk + a;
        if (aG < NADLA)
            av[((long long)bh * NADLA + aG) * HD + d] = Osm[a * 50 + d] * lnv[a];
    }
}

// ---------------- fused attention 2: 64 rows/CTA, anchors resident ----------------
#define A2_U   0               // AthT[48][352] then V[343][52]
#define A2_LS  17900           // Ls[64][360]
#define A2_QS  40940           // qT[48][66] then Osm[64][50]
#define A2_LNV 44140
#define A2_BYTES (44204*4)

__global__ void __launch_bounds__(512, 1) fused_att2(
    const float* __restrict__ q, const float* __restrict__ adla,
    const float* __restrict__ av, const float* __restrict__ ab,
    float* __restrict__ attn)
{
    extern __shared__ float sm[];
    float* U   = sm + A2_U;
    float* Ls  = sm + A2_LS;
    float* QS  = sm + A2_QS;
    float* lnv = sm + A2_LNV;

    const int bh = blockIdx.y, b = bh >> 3, h = bh & 7;
    const int n0 = blockIdx.x * 64;
    const int tid = threadIdx.x;

    for (int i = tid; i < 48 * 352; i += 512) {
        int d = i / 352, a = i - d * 352;
        U[i] = (a < NADLA) ? adla[((long long)(b * NADLA + a)) * DIMC + h * HD + d] : 0.f;
    }
    for (int i = tid; i < 64 * 48; i += 512) {
        int r = i / 48, d = i - r * 48;
        int n = n0 + r; int nC = n < NTOK ? n : NTOK - 1;
        QS[d * 66 + r] = q[((long long)(b * NTOK + nC)) * DIMC + h * HD + d] * SCALE;
    }
    __syncthreads();

    // phase A: thread = 4 rows x 22 anchors, 2-way d-split
    {
        const int dsel = tid >> 8, rem = tid & 255;
        const int r0 = (rem >> 4) * 4, a0 = (rem & 15) * 22;
        float2 acc[4][11];
#pragma unroll
        for (int i = 0; i < 4; i++)
#pragma unroll
            for (int j = 0; j < 11; j++) acc[i][j] = make_float2(0.f, 0.f);
        const int dbase = dsel * 24;
#pragma unroll 2
        for (int dd = 0; dd < 24; dd++) {
            int d = dbase + dd;
            float2 q01 = *(const float2*)&QS[d * 66 + r0];
            float2 q23 = *(const float2*)&QS[d * 66 + r0 + 2];
            float2 Q0 = make_float2(q01.x, q01.x), Q1 = make_float2(q01.y, q01.y);
            float2 Q2 = make_float2(q23.x, q23.x), Q3 = make_float2(q23.y, q23.y);
            const float* ar = &U[d * 352 + a0];
#pragma unroll
            for (int j = 0; j < 11; j++) {
                float2 Ar = *(const float2*)(ar + 2 * j);
                fma2(acc[0][j], Q0, Ar); fma2(acc[1][j], Q1, Ar);
                fma2(acc[2][j], Q2, Ar); fma2(acc[3][j], Q3, Ar);
            }
        }
        if (dsel == 0) {
#pragma unroll
            for (int i = 0; i < 4; i++) {
                int n = n0 + r0 + i; int nC = n < NTOK ? n : NTOK - 1;
                const float* abr = ab + ((long long)(h * NTOK + nC)) * NADLA;
#pragma unroll
                for (int j = 0; j < 11; j++) {
                    int a = a0 + 2 * j;
                    if (a < NADLA)     Ls[(r0 + i) * 360 + a]     = acc[i][j].x + abr[a];
                    if (a + 1 < NADLA) Ls[(r0 + i) * 360 + a + 1] = acc[i][j].y + abr[a + 1];
                }
            }
        }
        __syncthreads();
        if (dsel == 1) {
#pragma unroll
            for (int i = 0; i < 4; i++)
#pragma unroll
                for (int j = 0; j < 11; j++) {
                    int a = a0 + 2 * j;
                    if (a < NADLA)     Ls[(r0 + i) * 360 + a]     += acc[i][j].x;
                    if (a + 1 < NADLA) Ls[(r0 + i) * 360 + a + 1] += acc[i][j].y;
                }
        }
        __syncthreads();
    }

    // stage V into U (AthT dead) + phase B softmax
    for (int i = tid; i < NADLA * 48; i += 512) {
        int a = i / 48, c = i - a * 48;
        U[a * 52 + c] = av[((long long)bh * NADLA + a) * HD + c];
    }
    {
        const int r = tid >> 3, t8 = tid & 7;
        float mx = -INFINITY;
        for (int a = t8; a < NADLA; a += 8) mx = fmaxf(mx, Ls[r * 360 + a]);
#pragma unroll
        for (int o = 1; o < 8; o <<= 1)
            mx = fmaxf(mx, __shfl_xor_sync(0xffffffffu, mx, o));
        float sum = 0.f;
        for (int a = t8; a < NADLA; a += 8) {
            float pv = __expf(Ls[r * 360 + a] - mx);
            Ls[r * 360 + a] = pv;
            sum += pv;
        }
#pragma unroll
        for (int o = 1; o < 8; o <<= 1)
            sum += __shfl_xor_sync(0xffffffffu, sum, o);
        if (t8 == 0) lnv[r] = 1.f / sum;
    }
    __syncthreads();

    // phase C: thread = 8 rows x 6 dims, anchor-eighth
    {
        const int d0 = (tid & 7) * 6;
        const int as = (tid >> 3) & 7;
        const int r0 = (tid >> 6) * 8;
        float2 acc[8][3];
#pragma unroll
        for (int i = 0; i < 8; i++) acc[i][0] = acc[i][1] = acc[i][2] = make_float2(0.f, 0.f);
        for (int a = as; a < NADLA; a += 8) {
            const float* vr = &U[a * 52 + d0];
            float2 v0 = *(const float2*)(vr);
            float2 v1 = *(const float2*)(vr + 2);
            float2 v2 = *(const float2*)(vr + 4);
#pragma unroll
            for (int i = 0; i < 8; i++) {
                float pv = Ls[(r0 + i) * 360 + a];
                float2 pp = make_float2(pv, pv);
                fma2(acc[i][0], pp, v0); fma2(acc[i][1], pp, v1); fma2(acc[i][2], pp, v2);
            }
        }
        __syncthreads();
        float* Osm = QS;  // [64][50]
        if (as == 0) {
#pragma unroll
            for (int i = 0; i < 8; i++) {
                float* dst = &Osm[(r0 + i) * 50 + d0];
                *(float2*)(dst) = acc[i][0]; *(float2*)(dst + 2) = acc[i][1]; *(float2*)(dst + 4) = acc[i][2];
            }
        }
        __syncthreads();
#pragma unroll
        for (int k = 1; k < 8; k++) {
            if (as == k) {
#pragma unroll
                for (int i = 0; i < 8; i++) {
                    float* dst = &Osm[(r0 + i) * 50 + d0];
                    float2 t0 = *(float2*)(dst), t1 = *(float2*)(dst + 2), t2 = *(float2*)(dst + 4);
                    t0.x += acc[i][0].x; t0.y += acc[i][0].y;
                    t1.x += acc[i][1].x; t1.y += acc[i][1].y;
                    t2.x += acc[i][2].x; t2.y += acc[i][2].y;
                    *(float2*)(dst) = t0; *(float2*)(dst + 2) = t1; *(float2*)(dst + 4) = t2;
                }
            }
            __syncthreads();
        }
    }
    for (int i = tid; i < 64 * 48; i += 512) {
        int r = i / 48, d = i - r * 48;
        int n = n0 + r;
        if (n < NTOK)
            attn[((long long)(b * NTOK + n)) * DIMC + h * HD + d] = QS[r * 50 + d] * lnv[r];
    }
}

// ---------------- pooling ----------------
__global__ void pool_adla(const float* __restrict__ q, float* __restrict__ adla)
{
    int idx = blockIdx.x * 256 + threadIdx.x;
    if (idx >= BATCH * NADLA * DIMC) return;
    int c = idx % DIMC;
    int a = (idx / DIMC) % NADLA;
    int b = idx / (DIMC * NADLA);
    int a1 = a / 49, a2 = (a / 7) % 7, a3 = a % 7;
    float s = 0.f;
#pragma unroll
    for (int i = 0; i < 2; i++)
#pragma unroll
        for (int j = 0; j < 2; j++)
#pragma unroll
            for (int k = 0; k < 2; k++) {
                int n = ((2 * a1 + i) * HWD + (2 * a2 + j)) * HWD + (2 * a3 + k);
                s += q[((long long)(b * NTOK + n)) * DIMC + c];
            }
    adla[idx] = s * 0.125f;
}

// ---------------- bias tables ----------------
__device__ __forceinline__ void lin_w(int o, int& i0, int& i1, float& w)
{
    float x = 0.5f * o - 0.25f;
    x = fminf(fmaxf(x, 0.f), 6.f);
    i0 = (int)floorf(x);
    i1 = min(i0 + 1, 6);
    w = x - (float)i0;
}

__device__ __forceinline__ float interp3(const float* base, int x, int y, int z)
{
    int x0, x1, y0, y1, z0, z1;
    float wx, wy, wz;
    lin_w(x, x0, x1, wx); lin_w(y, y0, y1, wy); lin_w(z, z0, z1, wz);
    float c000 = base[x0 * 49 + y0 * 7 + z0], c001 = base[x0 * 49 + y0 * 7 + z1];
    float c010 = base[x0 * 49 + y1 * 7 + z0], c011 = base[x0 * 49 + y1 * 7 + z1];
    float c100 = base[x1 * 49 + y0 * 7 + z0], c101 = base[x1 * 49 + y0 * 7 + z1];
    float c110 = base[x1 * 49 + y1 * 7 + z0], c111 = base[x1 * 49 + y1 * 7 + z1];
    float v0 = (1.f - wy) * ((1.f - wz) * c000 + wz * c001) + wy * ((1.f - wz) * c010 + wz * c011);
    float v1 = (1.f - wy) * ((1.f - wz) * c100 + wz * c101) + wy * ((1.f - wz) * c110 + wz * c111);
    return (1.f - wx) * v0 + wx * v1;
}

__global__ void pb_kernel(const float* __restrict__ an, const float* __restrict__ ah,
                          const float* __restrict__ aw, const float* __restrict__ ad,
                          float* __restrict__ pb)
{
    int idx = blockIdx.x * 256 + threadIdx.x;
    if (idx >= HEADS * NADLA * NTOK) return;
    int n = idx % NTOK;
    int a = (idx / NTOK) % NADLA;
    int h = idx / (NTOK * NADLA);
    int x = n / 196, y = (n / 14) % 14, z = n % 14;
    const float* base = an + ((long long)(h * NADLA + a)) * NADLA;
    float v = interp3(base, x, y, z);
    v += ah[(h * NADLA + a) * HWD + x];
    v += aw[(h * NADLA + a) * HWD + y];
    v += ad[(h * NADLA + a) * HWD + z];
    pb[idx] = v;
}

__global__ void ab_kernel(const float* __restrict__ na, const float* __restrict__ ha,
                          const float* __restrict__ wa, const float* __restrict__ da,
                          float* __restrict__ ab)
{
    int idx = blockIdx.x * 256 + threadIdx.x;
    if (idx >= HEADS * NTOK * NADLA) return;
    int a = idx % NADLA;
    int n = (idx / NADLA) % NTOK;
    int h = idx / (NADLA * NTOK);
    int x = n / 196, y = (n / 14) % 14, z = n % 14;
    const float* base = na + ((long long)(h * NADLA + a)) * NADLA;
    float v = interp3(base, x, y, z);
    v += ha[(h * HWD + x) * NADLA + a];
    v += wa[(h * HWD + y) * NADLA + a];
    v += da[(h * HWD + z) * NADLA + a];
    ab[idx] = v;
}

// ---------------- depthwise 3x3x3 conv, += into attn ----------------
__global__ void dwc_add(const float* __restrict__ kv, const float* __restrict__ w,
                        const float* __restrict__ bias, float* __restrict__ attn)
{
    int blk = blockIdx.x;
    int c = threadIdx.x;
    int b = blk / NTOK, n = blk % NTOK;
    int x = n / 196, y = (n / 14) % 14, z = n % 14;
    float acc = bias[c];
    const float* wc = w + c * 27;
#pragma unroll
    for (int i = -1; i <= 1; i++) {
        int xx = x + i;
        if ((unsigned)xx >= (unsigned)HWD) continue;
#pragma unroll
        for (int j = -1; j <= 1; j++) {
            int yy = y + j;
            if ((unsigned)yy >= (unsigned)HWD) continue;
#pragma unroll
            for (int k = -1; k <= 1; k++) {
                int zz = z + k;
                if ((unsigned)zz >= (unsigned)HWD) continue;
                int nn = (xx * HWD + yy) * HWD + zz;
                acc = fmaf(kv[((long long)(b * NTOK + nn)) * 768 + DIMC + c],
                           wc[(i + 1) * 9 + (j + 1) * 3 + (k + 1)], acc);
            }
        }
    }
    attn[(long long)blk * DIMC + c] += acc;
}

// ---------------- launcher ----------------
extern "C" void kernel_launch(void* const* d_in, const int* in_sizes, int n_in,
                              void* d_out, int out_size)
{
    const float* x     = (const float*)d_in[0];
    const float* Wq    = (const float*)d_in[1];
    const float* Wkv   = (const float*)d_in[2];
    const float* Wproj = (const float*)d_in[3];
    const float* bproj = (const float*)d_in[4];
    const float* dwcw  = (const float*)d_in[5];
    const float* dwcb  = (const float*)d_in[6];
    const float* an    = (const float*)d_in[7];
    const float* na    = (const float*)d_in[8];
    const float* ah    = (const float*)d_in[9];
    const float* aw    = (const float*)d_in[10];
    const float* ad    = (const float*)d_in[11];
    const float* ha    = (const float*)d_in[12];
    const float* wa    = (const float*)d_in[13];
    const float* da    = (const float*)d_in[14];
    float* out = (float*)d_out;

    void* p;
    cudaGetSymbolAddress(&p, g_q);     float* q    = (float*)p;
    cudaGetSymbolAddress(&p, g_kv);    float* kv   = (float*)p;
    cudaGetSymbolAddress(&p, g_adla);  float* adla = (float*)p;
    cudaGetSymbolAddress(&p, g_pb);    float* pb   = (float*)p;
    cudaGetSymbolAddress(&p, g_ab);    float* ab   = (float*)p;
    cudaGetSymbolAddress(&p, g_adlav); float* av   = (float*)p;
    cudaGetSymbolAddress(&p, g_attn);  float* at   = (float*)p;

    cudaFuncSetAttribute(fused_att1, cudaFuncAttributeMaxDynamicSharedMemorySize, A1_BYTES);
    cudaFuncSetAttribute(fused_att2, cudaFuncAttributeMaxDynamicSharedMemorySize, A2_BYTES);

    sgemm_f2<<<dim3(DIMC / 128, cdiv(MTOT, 128)), 256>>>(x, Wq, q, nullptr, MTOT, DIMC, DIMC);
    sgemm_f2<<<dim3(768 / 128, cdiv(MTOT, 128)), 256>>>(x, Wkv, kv, nullptr, MTOT, 768, DIMC);
    pool_adla<<<cdiv(BATCH * NADLA * DIMC, 256), 256>>>(q, adla);
    pb_kernel<<<cdiv(HEADS * NADLA * NTOK, 256), 256>>>(an, ah, aw, ad, pb);
    ab_kernel<<<cdiv(HEADS * NTOK * NADLA, 256), 256>>>(na, ha, wa, da, ab);
    fused_att1<<<dim3(cdiv(NADLA, 64), BATCH * HEADS), 256, A1_BYTES>>>(adla, kv, pb, av);
    fused_att2<<<dim3(cdiv(NTOK, 64), BATCH * HEADS), 512, A2_BYTES>>>(q, adla, av, ab, at);
    dwc_add<<<BATCH * NTOK, DIMC>>>(kv, dwcw, dwcb, at);
    sgemm_f2<<<dim3(DIMC / 128, cdiv(MTOT, 128)), 256>>>(at, Wproj, out, bproj, MTOT, DIMC, DIMC);
}

// round 11
// speedup vs baseline: 1.1009x; 1.0626x over previous
#include <cuda_runtime.h>
#include <cuda_bf16.h>
#include <math.h>
#include <stdint.h>
#include <string.h>

#define DIMC   384
#define HEADS  8
#define HD     48
#define NADLA  343
#define HWD    14
#define NTOK   2744
#define BATCH  8
#define MTOT   (BATCH*NTOK)
#define SCALE  0.14433756729740643f

__device__ float g_q   [(long long)MTOT*DIMC];
__device__ float g_kv  [(long long)MTOT*2*DIMC];
__device__ float g_adla[(long long)BATCH*NADLA*DIMC];
__device__ float g_pb  [(long long)HEADS*NADLA*NTOK];
__device__ float g_ab  [(long long)HEADS*NTOK*NADLA];
__device__ float g_adlav[(long long)BATCH*HEADS*NADLA*HD];
__device__ float g_attn[(long long)MTOT*DIMC];

static inline int cdiv(int a, int b) { return (a + b - 1) / b; }

__device__ __forceinline__ void fma2(float2& c, float2 a, float2 b)
{
    unsigned long long cc, aa, bb;
    memcpy(&cc, &c, 8); memcpy(&aa, &a, 8); memcpy(&bb, &b, 8);
    asm("fma.rn.f32x2 %0, %1, %2, %0;" : "+l"(cc) : "l"(aa), "l"(bb));
    memcpy(&c, &cc, 8);
}

// ---------------- dense NN sgemm (f32x2), tile 128x64x16, 8x4 thread tile,
// register-prefetch double buffering (12 prefetch floats -> no spill) ----------------
__global__ void __launch_bounds__(256)
sgemm_f2(const float* __restrict__ A, const float* __restrict__ B,
         float* __restrict__ C, const float* __restrict__ bias,
         int M, int N, int K)
{
    __shared__ float As[16][132];   // As[k][m]
    __shared__ float Bs[16][68];    // Bs[k][n]

    const int tid = threadIdx.x, tx = tid & 15, ty = tid >> 4;
    const int row0 = blockIdx.y * 128, col0 = blockIdx.x * 64;

    // staging maps
    const int ar0 = (tid + 0)   >> 2, akq0 = ((tid + 0)   & 3) << 2;
    const int ar1 = (tid + 256) >> 2, akq1 = ((tid + 256) & 3) << 2;
    const int bkk = tid >> 4,  bnq = (tid & 15) << 2;

    float4 pA0, pA1, pB;

    auto ld = [&](int k0) {
        int gr0 = row0 + ar0;
        pA0 = (gr0 < M) ? *(const float4*)(A + (long long)gr0 * K + k0 + akq0)
                        : make_float4(0.f, 0.f, 0.f, 0.f);
        int gr1 = row0 + ar1;
        pA1 = (gr1 < M) ? *(const float4*)(A + (long long)gr1 * K + k0 + akq1)
                        : make_float4(0.f, 0.f, 0.f, 0.f);
        pB = *(const float4*)(B + (long long)(k0 + bkk) * N + col0 + bnq);
    };
    auto st = [&]() {
        As[akq0 + 0][ar0] = pA0.x; As[akq0 + 1][ar0] = pA0.y;
        As[akq0 + 2][ar0] = pA0.z; As[akq0 + 3][ar0] = pA0.w;
        As[akq1 + 0][ar1] = pA1.x; As[akq1 + 1][ar1] = pA1.y;
        As[akq1 + 2][ar1] = pA1.z; As[akq1 + 3][ar1] = pA1.w;
        *(float4*)&Bs[bkk][bnq] = pB;
    };

    float2 acc[4][4];
#pragma unroll
    for (int i = 0; i < 4; i++)
#pragma unroll
        for (int j = 0; j < 4; j++) acc[i][j] = make_float2(0.f, 0.f);

    ld(0);
    st();
    __syncthreads();

    for (int k0 = 16;; k0 += 16) {
        bool more = k0 < K;
        if (more) ld(k0);
#pragma unroll
        for (int kk = 0; kk < 16; kk++) {
            float2 a2[4];
#pragma unroll
            for (int i = 0; i < 4; i++) a2[i] = *(const float2*)&As[kk][ty * 8 + 2 * i];
            float2 b01 = *(const float2*)&Bs[kk][tx * 4];
            float2 b23 = *(const float2*)&Bs[kk][tx * 4 + 2];
            float2 bb[4] = { make_float2(b01.x, b01.x), make_float2(b01.y, b01.y),
                             make_float2(b23.x, b23.x), make_float2(b23.y, b23.y) };
#pragma unroll
            for (int i = 0; i < 4; i++)
#pragma unroll
                for (int j = 0; j < 4; j++) fma2(acc[i][j], a2[i], bb[j]);
        }
        if (!more) break;
        __syncthreads();
        st();
        __syncthreads();
    }

#pragma unroll
    for (int i = 0; i < 4; i++) {
        int gr0 = row0 + ty * 8 + 2 * i, gc = col0 + tx * 4;
        float bx[4] = {0, 0, 0, 0};
        if (bias) {
#pragma unroll
            for (int j = 0; j < 4; j++) bx[j] = bias[gc + j];
        }
        if (gr0 < M)
            *(float4*)(C + (long long)gr0 * N + gc) =
                make_float4(acc[i][0].x + bx[0], acc[i][1].x + bx[1],
                            acc[i][2].x + bx[2], acc[i][3].x + bx[3]);
        if (gr0 + 1 < M)
            *(float4*)(C + (long long)(gr0 + 1) * N + gc) =
                make_float4(acc[i][0].y + bx[0], acc[i][1].y + bx[1],
                            acc[i][2].y + bx[2], acc[i][3].y + bx[3]);
    }
}

// ---------------- fused attention 1: 64 anchors/CTA, 128-token chunks ----------------
#define A1_ATH 0
#define A1_KST 3168            // [48][130]
#define A1_VS  9408            // [128][52]
#define A1_PS  16064           // [64][132]; reused as Osm [64][50]
#define A1_FAC 24512
#define A1_LNV 24576
#define A1_BYTES (24640*4)

__global__ void __launch_bounds__(256, 2) fused_att1(
    const float* __restrict__ adla, const float* __restrict__ kv,
    const float* __restrict__ pb, float* __restrict__ av)
{
    extern __shared__ float sm[];
    float* AthT = sm + A1_ATH;
    float* KsT  = sm + A1_KST;
    float* Vs   = sm + A1_VS;
    float* Ps   = sm + A1_PS;
    float* facs = sm + A1_FAC;
    float* lnv  = sm + A1_LNV;

    const int bh = blockIdx.y, b = bh >> 3, h = bh & 7;
    const int a0blk = blockIdx.x * 64;
    const int tid = threadIdx.x;
    const int a4 = (tid >> 4) * 4, tg = tid & 15;
    const int d0 = (tid & 7) * 6, ts = (tid >> 3) & 3, a8 = (tid >> 5) * 8;
    const int srow = tid >> 1, scol = (tid & 1) * 24;

    for (int i = tid; i < 64 * 48; i += 256) {
        int a = i / 48, d = i - a * 48;
        int aG = a0blk + a;
        AthT[d * 66 + a] = (aG < NADLA)
            ? adla[((long long)(b * NADLA + aG)) * DIMC + h * HD + d] * SCALE : 0.f;
    }

    const float* pbr[4];
#pragma unroll
    for (int i = 0; i < 4; i++) {
        int aG = a0blk + a4 + i;
        pbr[i] = pb + ((long long)(h * NADLA + (aG < NADLA ? aG : NADLA - 1))) * NTOK;
    }

    float m[4], l[4];
#pragma unroll
    for (int i = 0; i < 4; i++) { m[i] = -INFINITY; l[i] = 0.f; }
    float2 O[8][3];
#pragma unroll
    for (int i = 0; i < 8; i++) O[i][0] = O[i][1] = O[i][2] = make_float2(0.f, 0.f);

    for (int c0 = 0; c0 < NTOK; c0 += 128) {
        {   // stage K^T and V
            int n = c0 + srow;
            bool ok = n < NTOK;
            const float* kb = kv + ((long long)(b * NTOK + (ok ? n : 0))) * 768 + h * HD + scol;
#pragma unroll
            for (int j = 0; j < 24; j += 4) {
                float4 kk = ok ? *(const float4*)(kb + j) : make_float4(0, 0, 0, 0);
                float4 vv = ok ? *(const float4*)(kb + 384 + j) : make_float4(0, 0, 0, 0);
                KsT[(scol + j + 0) * 130 + srow] = kk.x;
                KsT[(scol + j + 1) * 130 + srow] = kk.y;
                KsT[(scol + j + 2) * 130 + srow] = kk.z;
                KsT[(scol + j + 3) * 130 + srow] = kk.w;
                *(float4*)&Vs[srow * 52 + scol + j] = vv;
            }
        }
        __syncthreads();

        // S: thread = 4 anchors x 8 tokens (strided by 16)
        float2 acc[8][2];
#pragma unroll
        for (int j = 0; j < 8; j++) acc[j][0] = acc[j][1] = make_float2(0.f, 0.f);
#pragma unroll 4
        for (int d = 0; d < 48; d++) {
            float2 aL = *(const float2*)&AthT[d * 66 + a4];
            float2 aH = *(const float2*)&AthT[d * 66 + a4 + 2];
            const float* kr = &KsT[d * 130 + tg];
#pragma unroll
            for (int j = 0; j < 8; j++) {
                float kx = kr[16 * j];
                float2 kk = make_float2(kx, kx);
                fma2(acc[j][0], aL, kk);
                fma2(acc[j][1], aH, kk);
            }
        }
#pragma unroll
        for (int i = 0; i < 4; i++) {
            float s[8];
            float mx = -INFINITY;
#pragma unroll
            for (int j = 0; j < 8; j++) {
                int n = c0 + tg + 16 * j;
                float sv = (i & 1) ? acc[j][i >> 1].y : acc[j][i >> 1].x;
                s[j] = (n < NTOK) ? sv + pbr[i][n] : -INFINITY;
                mx = fmaxf(mx, s[j]);
            }
#pragma unroll
            for (int o = 1; o < 16; o <<= 1)
                mx = fmaxf(mx, __shfl_xor_sync(0xffffffffu, mx, o));
            float mn = fmaxf(m[i], mx);
            float sum = 0.f;
#pragma unroll
            for (int j = 0; j < 8; j++) {
                float pv = __expf(s[j] - mn);
                Ps[(a4 + i) * 132 + tg + 16 * j] = pv;
                sum += pv;
            }
#pragma unroll
            for (int o = 1; o < 16; o <<= 1)
                sum += __shfl_xor_sync(0xffffffffu, sum, o);
            float fac = __expf(m[i] - mn);
            l[i] = l[i] * fac + sum;
            m[i] = mn;
            if (tg == 0) facs[a4 + i] = fac;
        }
        __syncthreads();

        // O: thread = 8 anchors x 6 dims, token-quarter ts
        {
#pragma unroll
            for (int i = 0; i < 8; i++) {
                float f = facs[a8 + i];
                O[i][0].x *= f; O[i][0].y *= f;
                O[i][1].x *= f; O[i][1].y *= f;
                O[i][2].x *= f; O[i][2].y *= f;
            }
#pragma unroll 2
            for (int jj = 0; jj < 32; jj++) {
                int j = 4 * jj + ts;
                const float* vr = &Vs[j * 52 + d0];
                float2 v0 = *(const float2*)(vr);
                float2 v1 = *(const float2*)(vr + 2);
                float2 v2 = *(const float2*)(vr + 4);
#pragma unroll
                for (int i = 0; i < 8; i++) {
                    float p = Ps[(a8 + i) * 132 + j];
                    float2 pp = make_float2(p, p);
                    fma2(O[i][0], pp, v0);
                    fma2(O[i][1], pp, v1);
                    fma2(O[i][2], pp, v2);
                }
            }
        }
        __syncthreads();
    }

    if (tg == 0) {
#pragma unroll
        for (int i = 0; i < 4; i++) lnv[a4 + i] = 1.f / l[i];
    }
    float* Osm = Ps;  // [64][50]
    if (ts == 0) {
#pragma unroll
        for (int i = 0; i < 8; i++) {
            float* dst = &Osm[(a8 + i) * 50 + d0];
            *(float2*)(dst) = O[i][0]; *(float2*)(dst + 2) = O[i][1]; *(float2*)(dst + 4) = O[i][2];
        }
    }
    __syncthreads();
#pragma unroll
    for (int k = 1; k < 4; k++) {
        if (ts == k) {
#pragma unroll
            for (int i = 0; i < 8; i++) {
                float* dst = &Osm[(a8 + i) * 50 + d0];
                float2 t0 = *(float2*)(dst), t1 = *(float2*)(dst + 2), t2 = *(float2*)(dst + 4);
                t0.x += O[i][0].x; t0.y += O[i][0].y;
                t1.x += O[i][1].x; t1.y += O[i][1].y;
                t2.x += O[i][2].x; t2.y += O[i][2].y;
                *(float2*)(dst) = t0; *(float2*)(dst + 2) = t1; *(float2*)(dst + 4) = t2;
            }
        }
        __syncthreads();
    }
    for (int i = tid; i < 64 * 48; i += 256) {
        int a = i / 48, d = i - a * 48;
        int aG = a0blk + a;
        if (aG < NADLA)
            av[((long long)bh * NADLA + aG) * HD + d] = Osm[a * 50 + d] * lnv[a];
    }
}

// ---------------- fused attention 2: 64 rows/CTA, anchors resident ----------------
#define A2_U   0               // AthT[48][352] then V[343][52]
#define A2_LS  17900           // Ls[64][360]
#define A2_QS  40940           // qT[48][66] then Osm[64][50]
#define A2_LNV 44140
#define A2_BYTES (44204*4)

__global__ void __launch_bounds__(512, 1) fused_att2(
    const float* __restrict__ q, const float* __restrict__ adla,
    const float* __restrict__ av, const float* __restrict__ ab,
    float* __restrict__ attn)
{
    extern __shared__ float sm[];
    float* U   = sm + A2_U;
    float* Ls  = sm + A2_LS;
    float* QS  = sm + A2_QS;
    float* lnv = sm + A2_LNV;

    const int bh = blockIdx.y, b = bh >> 3, h = bh & 7;
    const int n0 = blockIdx.x * 64;
    const int tid = threadIdx.x;

    for (int i = tid; i < 48 * 352; i += 512) {
        int d = i / 352, a = i - d * 352;
        U[i] = (a < NADLA) ? adla[((long long)(b * NADLA + a)) * DIMC + h * HD + d] : 0.f;
    }
    for (int i = tid; i < 64 * 48; i += 512) {
        int r = i / 48, d = i - r * 48;
        int n = n0 + r; int nC = n < NTOK ? n : NTOK - 1;
        QS[d * 66 + r] = q[((long long)(b * NTOK + nC)) * DIMC + h * HD + d] * SCALE;
    }
    __syncthreads();

    // phase A: thread = 4 rows x 22 anchors, 2-way d-split
    {
        const int dsel = tid >> 8, rem = tid & 255;
        const int r0 = (rem >> 4) * 4, a0 = (rem & 15) * 22;
        float2 acc[4][11];
#pragma unroll
        for (int i = 0; i < 4; i++)
#pragma unroll
            for (int j = 0; j < 11; j++) acc[i][j] = make_float2(0.f, 0.f);
        const int dbase = dsel * 24;
#pragma unroll 2
        for (int dd = 0; dd < 24; dd++) {
            int d = dbase + dd;
            float2 q01 = *(const float2*)&QS[d * 66 + r0];
            float2 q23 = *(const float2*)&QS[d * 66 + r0 + 2];
            float2 Q0 = make_float2(q01.x, q01.x), Q1 = make_float2(q01.y, q01.y);
            float2 Q2 = make_float2(q23.x, q23.x), Q3 = make_float2(q23.y, q23.y);
            const float* ar = &U[d * 352 + a0];
#pragma unroll
            for (int j = 0; j < 11; j++) {
                float2 Ar = *(const float2*)(ar + 2 * j);
                fma2(acc[0][j], Q0, Ar); fma2(acc[1][j], Q1, Ar);
                fma2(acc[2][j], Q2, Ar); fma2(acc[3][j], Q3, Ar);
            }
        }
        if (dsel == 0) {
#pragma unroll
            for (int i = 0; i < 4; i++) {
                int n = n0 + r0 + i; int nC = n < NTOK ? n : NTOK - 1;
                const float* abr = ab + ((long long)(h * NTOK + nC)) * NADLA;
#pragma unroll
                for (int j = 0; j < 11; j++) {
                    int a = a0 + 2 * j;
                    if (a < NADLA)     Ls[(r0 + i) * 360 + a]     = acc[i][j].x + abr[a];
                    if (a + 1 < NADLA) Ls[(r0 + i) * 360 + a + 1] = acc[i][j].y + abr[a + 1];
                }
            }
        }
        __syncthreads();
        if (dsel == 1) {
#pragma unroll
            for (int i = 0; i < 4; i++)
#pragma unroll
                for (int j = 0; j < 11; j++) {
                    int a = a0 + 2 * j;
                    if (a < NADLA)     Ls[(r0 + i) * 360 + a]     += acc[i][j].x;
                    if (a + 1 < NADLA) Ls[(r0 + i) * 360 + a + 1] += acc[i][j].y;
                }
        }
        __syncthreads();
    }

    // stage V into U (AthT dead) + phase B softmax
    for (int i = tid; i < NADLA * 48; i += 512) {
        int a = i / 48, c = i - a * 48;
        U[a * 52 + c] = av[((long long)bh * NADLA + a) * HD + c];
    }
    {
        const int r = tid >> 3, t8 = tid & 7;
        float mx = -INFINITY;
        for (int a = t8; a < NADLA; a += 8) mx = fmaxf(mx, Ls[r * 360 + a]);
#pragma unroll
        for (int o = 1; o < 8; o <<= 1)
            mx = fmaxf(mx, __shfl_xor_sync(0xffffffffu, mx, o));
        float sum = 0.f;
        for (int a = t8; a < NADLA; a += 8) {
            float pv = __expf(Ls[r * 360 + a] - mx);
            Ls[r * 360 + a] = pv;
            sum += pv;
        }
#pragma unroll
        for (int o = 1; o < 8; o <<= 1)
            sum += __shfl_xor_sync(0xffffffffu, sum, o);
        if (t8 == 0) lnv[r] = 1.f / sum;
    }
    __syncthreads();

    // phase C: thread = 8 rows x 6 dims, anchor-eighth
    {
        const int d0 = (tid & 7) * 6;
        const int as = (tid >> 3) & 7;
        const int r0 = (tid >> 6) * 8;
        float2 acc[8][3];
#pragma unroll
        for (int i = 0; i < 8; i++) acc[i][0] = acc[i][1] = acc[i][2] = make_float2(0.f, 0.f);
        for (int a = as; a < NADLA; a += 8) {
            const float* vr = &U[a * 52 + d0];
            float2 v0 = *(const float2*)(vr);
            float2 v1 = *(const float2*)(vr + 2);
            float2 v2 = *(const float2*)(vr + 4);
#pragma unroll
            for (int i = 0; i < 8; i++) {
                float pv = Ls[(r0 + i) * 360 + a];
                float2 pp = make_float2(pv, pv);
                fma2(acc[i][0], pp, v0); fma2(acc[i][1], pp, v1); fma2(acc[i][2], pp, v2);
            }
        }
        __syncthreads();
        float* Osm = QS;  // [64][50]
        if (as == 0) {
#pragma unroll
            for (int i = 0; i < 8; i++) {
                float* dst = &Osm[(r0 + i) * 50 + d0];
                *(float2*)(dst) = acc[i][0]; *(float2*)(dst + 2) = acc[i][1]; *(float2*)(dst + 4) = acc[i][2];
            }
        }
        __syncthreads();
#pragma unroll
        for (int k = 1; k < 8; k++) {
            if (as == k) {
#pragma unroll
                for (int i = 0; i < 8; i++) {
                    float* dst = &Osm[(r0 + i) * 50 + d0];
                    float2 t0 = *(float2*)(dst), t1 = *(float2*)(dst + 2), t2 = *(float2*)(dst + 4);
                    t0.x += acc[i][0].x; t0.y += acc[i][0].y;
                    t1.x += acc[i][1].x; t1.y += acc[i][1].y;
                    t2.x += acc[i][2].x; t2.y += acc[i][2].y;
                    *(float2*)(dst) = t0; *(float2*)(dst + 2) = t1; *(float2*)(dst + 4) = t2;
                }
            }
            __syncthreads();
        }
    }
    for (int i = tid; i < 64 * 48; i += 512) {
        int r = i / 48, d = i - r * 48;
        int n = n0 + r;
        if (n < NTOK)
            attn[((long long)(b * NTOK + n)) * DIMC + h * HD + d] = QS[r * 50 + d] * lnv[r];
    }
}

// ---------------- pooling ----------------
__global__ void pool_adla(const float* __restrict__ q, float* __restrict__ adla)
{
    int idx = blockIdx.x * 256 + threadIdx.x;
    if (idx >= BATCH * NADLA * DIMC) return;
    int c = idx % DIMC;
    int a = (idx / DIMC) % NADLA;
    int b = idx / (DIMC * NADLA);
    int a1 = a / 49, a2 = (a / 7) % 7, a3 = a % 7;
    float s = 0.f;
#pragma unroll
    for (int i = 0; i < 2; i++)
#pragma unroll
        for (int j = 0; j < 2; j++)
#pragma unroll
            for (int k = 0; k < 2; k++) {
                int n = ((2 * a1 + i) * HWD + (2 * a2 + j)) * HWD + (2 * a3 + k);
                s += q[((long long)(b * NTOK + n)) * DIMC + c];
            }
    adla[idx] = s * 0.125f;
}

// ---------------- bias tables ----------------
__device__ __forceinline__ void lin_w(int o, int& i0, int& i1, float& w)
{
    float x = 0.5f * o - 0.25f;
    x = fminf(fmaxf(x, 0.f), 6.f);
    i0 = (int)floorf(x);
    i1 = min(i0 + 1, 6);
    w = x - (float)i0;
}

__device__ __forceinline__ float interp3(const float* base, int x, int y, int z)
{
    int x0, x1, y0, y1, z0, z1;
    float wx, wy, wz;
    lin_w(x, x0, x1, wx); lin_w(y, y0, y1, wy); lin_w(z, z0, z1, wz);
    float c000 = base[x0 * 49 + y0 * 7 + z0], c001 = base[x0 * 49 + y0 * 7 + z1];
    float c010 = base[x0 * 49 + y1 * 7 + z0], c011 = base[x0 * 49 + y1 * 7 + z1];
    float c100 = base[x1 * 49 + y0 * 7 + z0], c101 = base[x1 * 49 + y0 * 7 + z1];
    float c110 = base[x1 * 49 + y1 * 7 + z0], c111 = base[x1 * 49 + y1 * 7 + z1];
    float v0 = (1.f - wy) * ((1.f - wz) * c000 + wz * c001) + wy * ((1.f - wz) * c010 + wz * c011);
    float v1 = (1.f - wy) * ((1.f - wz) * c100 + wz * c101) + wy * ((1.f - wz) * c110 + wz * c111);
    return (1.f - wx) * v0 + wx * v1;
}

__global__ void pb_kernel(const float* __restrict__ an, const float* __restrict__ ah,
                          const float* __restrict__ aw, const float* __restrict__ ad,
                          float* __restrict__ pb)
{
    int idx = blockIdx.x * 256 + threadIdx.x;
    if (idx >= HEADS * NADLA * NTOK) return;
    int n = idx % NTOK;
    int a = (idx / NTOK) % NADLA;
    int h = idx / (NTOK * NADLA);
    int x = n / 196, y = (n / 14) % 14, z = n % 14;
    const float* base = an + ((long long)(h * NADLA + a)) * NADLA;
    float v = interp3(base, x, y, z);
    v += ah[(h * NADLA + a) * HWD + x];
    v += aw[(h * NADLA + a) * HWD + y];
    v += ad[(h * NADLA + a) * HWD + z];
    pb[idx] = v;
}

__global__ void ab_kernel(const float* __restrict__ na, const float* __restrict__ ha,
                          const float* __restrict__ wa, const float* __restrict__ da,
                          float* __restrict__ ab)
{
    int idx = blockIdx.x * 256 + threadIdx.x;
    if (idx >= HEADS * NTOK * NADLA) return;
    int a = idx % NADLA;
    int n = (idx / NADLA) % NTOK;
    int h = idx / (NADLA * NTOK);
    int x = n / 196, y = (n / 14) % 14, z = n % 14;
    const float* base = na + ((long long)(h * NADLA + a)) * NADLA;
    float v = interp3(base, x, y, z);
    v += ha[(h * HWD + x) * NADLA + a];
    v += wa[(h * HWD + y) * NADLA + a];
    v += da[(h * HWD + z) * NADLA + a];
    ab[idx] = v;
}

// ---------------- depthwise 3x3x3 conv, += into attn ----------------
__global__ void dwc_add(const float* __restrict__ kv, const float* __restrict__ w,
                        const float* __restrict__ bias, float* __restrict__ attn)
{
    int blk = blockIdx.x;
    int c = threadIdx.x;
    int b = blk / NTOK, n = blk % NTOK;
    int x = n / 196, y = (n / 14) % 14, z = n % 14;
    float acc = bias[c];
    const float* wc = w + c * 27;
#pragma unroll
    for (int i = -1; i <= 1; i++) {
        int xx = x + i;
        if ((unsigned)xx >= (unsigned)HWD) continue;
#pragma unroll
        for (int j = -1; j <= 1; j++) {
            int yy = y + j;
            if ((unsigned)yy >= (unsigned)HWD) continue;
#pragma unroll
            for (int k = -1; k <= 1; k++) {
                int zz = z + k;
                if ((unsigned)zz >= (unsigned)HWD) continue;
                int nn = (xx * HWD + yy) * HWD + zz;
                acc = fmaf(kv[((long long)(b * NTOK + nn)) * 768 + DIMC + c],
                           wc[(i + 1) * 9 + (j + 1) * 3 + (k + 1)], acc);
            }
        }
    }
    attn[(long long)blk * DIMC + c] += acc;
}

// ---------------- launcher ----------------
extern "C" void kernel_launch(void* const* d_in, const int* in_sizes, int n_in,
                              void* d_out, int out_size)
{
    const float* x     = (const float*)d_in[0];
    const float* Wq    = (const float*)d_in[1];
    const float* Wkv   = (const float*)d_in[2];
    const float* Wproj = (const float*)d_in[3];
    const float* bproj = (const float*)d_in[4];
    const float* dwcw  = (const float*)d_in[5];
    const float* dwcb  = (const float*)d_in[6];
    const float* an    = (const float*)d_in[7];
    const float* na    = (const float*)d_in[8];
    const float* ah    = (const float*)d_in[9];
    const float* aw    = (const float*)d_in[10];
    const float* ad    = (const float*)d_in[11];
    const float* ha    = (const float*)d_in[12];
    const float* wa    = (const float*)d_in[13];
    const float* da    = (const float*)d_in[14];
    float* out = (float*)d_out;

    void* p;
    cudaGetSymbolAddress(&p, g_q);     float* q    = (float*)p;
    cudaGetSymbolAddress(&p, g_kv);    float* kv   = (float*)p;
    cudaGetSymbolAddress(&p, g_adla);  float* adla = (float*)p;
    cudaGetSymbolAddress(&p, g_pb);    float* pb   = (float*)p;
    cudaGetSymbolAddress(&p, g_ab);    float* ab   = (float*)p;
    cudaGetSymbolAddress(&p, g_adlav); float* av   = (float*)p;
    cudaGetSymbolAddress(&p, g_attn);  float* at   = (float*)p;

    cudaFuncSetAttribute(fused_att1, cudaFuncAttributeMaxDynamicSharedMemorySize, A1_BYTES);
    cudaFuncSetAttribute(fused_att2, cudaFuncAttributeMaxDynamicSharedMemorySize, A2_BYTES);

    sgemm_f2<<<dim3(DIMC / 64, cdiv(MTOT, 128)), 256>>>(x, Wq, q, nullptr, MTOT, DIMC, DIMC);
    sgemm_f2<<<dim3(768 / 64, cdiv(MTOT, 128)), 256>>>(x, Wkv, kv, nullptr, MTOT, 768, DIMC);
    pool_adla<<<cdiv(BATCH * NADLA * DIMC, 256), 256>>>(q, adla);
    pb_kernel<<<cdiv(HEADS * NADLA * NTOK, 256), 256>>>(an, ah, aw, ad, pb);
    ab_kernel<<<cdiv(HEADS * NTOK * NADLA, 256), 256>>>(na, ha, wa, da, ab);
    fused_att1<<<dim3(cdiv(NADLA, 64), BATCH * HEADS), 256, A1_BYTES>>>(adla, kv, pb, av);
    fused_att2<<<dim3(cdiv(NTOK, 64), BATCH * HEADS), 512, A2_BYTES>>>(q, adla, av, ab, at);
    dwc_add<<<BATCH * NTOK, DIMC>>>(kv, dwcw, dwcb, at);
    sgemm_f2<<<dim3(DIMC / 64, cdiv(MTOT, 128)), 256>>>(at, Wproj, out, bproj, MTOT, DIMC, DIMC);
}